// round 2
// baseline (speedup 1.0000x reference)
#include <cuda_runtime.h>
#include <math.h>

// Problem constants
#define BB 2
#define LL 1024
#define HH 256
#define NHEAD 8
#define DHEAD 32
#define FFD 1024
#define NLAYER 2
#define RELN 100
#define EPSLN 1e-5f
#define INV_SCALE 0.17677669529663687f   // 1/sqrt(32)

#define ROWS (BB*LL)          // 2048

// ---------------- scratch (static device memory; no allocations allowed) ----
__device__ float g_qb[ROWS*HH];
__device__ float g_kb[ROWS*HH];
__device__ float g_vb[ROWS*HH];
__device__ float g_ab[ROWS*HH];
__device__ float g_yb[ROWS*HH];
__device__ float g_xb[ROWS*HH];
__device__ float g_fb[ROWS*FFD];

// ---------------------------------------------------------------- GEMM -----
// C[M,N] = A[M,K] @ B[K,N] (+bias) (+relu). 64x64 tile, TK=16, 256 thr, 4x4.
__global__ __launch_bounds__(256) void gemm_kernel(
    const float* __restrict__ A, const float* __restrict__ B,
    const float* __restrict__ bias, float* __restrict__ C,
    int M, int N, int K, int doRelu)
{
    __shared__ float As[16][68];   // [k][m] transposed, padded
    __shared__ float Bs[16][68];   // [k][n], padded

    const int tid = threadIdx.x;
    const int tx = tid & 15;        // 0..15 -> n
    const int ty = tid >> 4;        // 0..15 -> m
    const int bm = blockIdx.y * 64;
    const int bn = blockIdx.x * 64;

    const int arow = tid >> 2;          // 0..63
    const int acol = (tid & 3) * 4;     // 0,4,8,12
    const int brow = tid >> 4;          // 0..15
    const int bcol = (tid & 15) * 4;    // 0..60

    float acc[4][4];
#pragma unroll
    for (int i = 0; i < 4; i++)
#pragma unroll
        for (int j = 0; j < 4; j++) acc[i][j] = 0.f;

    for (int k0 = 0; k0 < K; k0 += 16) {
        float4 av = *(const float4*)(A + (size_t)(bm + arow) * K + k0 + acol);
        As[acol + 0][arow] = av.x;
        As[acol + 1][arow] = av.y;
        As[acol + 2][arow] = av.z;
        As[acol + 3][arow] = av.w;
        float4 bv = *(const float4*)(B + (size_t)(k0 + brow) * N + bn + bcol);
        *(float4*)&Bs[brow][bcol] = bv;
        __syncthreads();
#pragma unroll
        for (int k = 0; k < 16; k++) {
            float a0 = As[k][ty * 4 + 0];
            float a1 = As[k][ty * 4 + 1];
            float a2 = As[k][ty * 4 + 2];
            float a3 = As[k][ty * 4 + 3];
            float4 b4 = *(const float4*)&Bs[k][tx * 4];
            acc[0][0] += a0 * b4.x; acc[0][1] += a0 * b4.y; acc[0][2] += a0 * b4.z; acc[0][3] += a0 * b4.w;
            acc[1][0] += a1 * b4.x; acc[1][1] += a1 * b4.y; acc[1][2] += a1 * b4.z; acc[1][3] += a1 * b4.w;
            acc[2][0] += a2 * b4.x; acc[2][1] += a2 * b4.y; acc[2][2] += a2 * b4.z; acc[2][3] += a2 * b4.w;
            acc[3][0] += a3 * b4.x; acc[3][1] += a3 * b4.y; acc[3][2] += a3 * b4.z; acc[3][3] += a3 * b4.w;
        }
        __syncthreads();
    }

    float bb0 = 0.f, bb1 = 0.f, bb2 = 0.f, bb3 = 0.f;
    if (bias) {
        const float4 b4 = *(const float4*)(bias + bn + tx * 4);
        bb0 = b4.x; bb1 = b4.y; bb2 = b4.z; bb3 = b4.w;
    }
#pragma unroll
    for (int i = 0; i < 4; i++) {
        float4 o;
        o.x = acc[i][0] + bb0;
        o.y = acc[i][1] + bb1;
        o.z = acc[i][2] + bb2;
        o.w = acc[i][3] + bb3;
        if (doRelu) {
            o.x = fmaxf(o.x, 0.f); o.y = fmaxf(o.y, 0.f);
            o.z = fmaxf(o.z, 0.f); o.w = fmaxf(o.w, 0.f);
        }
        *(float4*)(C + (size_t)(bm + ty * 4 + i) * N + bn + tx * 4) = o;
    }
}

// ----------------------------------------------------------- Attention -----
// Block: (i-tile of 16 rows, one batch). 256 threads:
//   half = tid>>7 processes one half of the 1024 j positions (split-K)
//   within a half: pair = tid&127, h = pair>>4 (8 heads), il = pair&15 (16 rows)
// Online softmax with per-(i,j) relation gather from smem.
#define TI 16
#define TJA 16

// smem float offsets
#define SM_EK   0                   // 100*33 = 3300
#define SM_EV   3300                // 3300
#define SM_KT   6600                // 2*16*256 = 8192
#define SM_VT   14792               // 8192
#define SM_RI   22984               // 512 ints
#define SM_MK   23496               // 512 ints (mask as int32)
#define ATTN_SMEM_FLOATS 24008
#define ATTN_SMEM_BYTES  (ATTN_SMEM_FLOATS*4)

__global__ __launch_bounds__(256, 1) void attn_kernel(
    const float* __restrict__ Q, const float* __restrict__ Kk,
    const float* __restrict__ V, const float* __restrict__ Ek,
    const float* __restrict__ Ev, const int* __restrict__ rel,
    const int* __restrict__ relmask, float* __restrict__ O)
{
    extern __shared__ float sm[];
    float* Eks = sm + SM_EK;                 // [100][33]
    float* Evs = sm + SM_EV;
    float* Kt  = sm + SM_KT;                 // [2][16][256]
    float* Vt  = sm + SM_VT;
    int*   ri  = (int*)(sm + SM_RI);         // [2][16][16]
    int*   mk  = (int*)(sm + SM_MK);         // [2][16][16]

    const int tid = threadIdx.x;
    const int b   = blockIdx.y;
    const int i0  = blockIdx.x * TI;
    const int hf  = tid >> 7;
    const int pr  = tid & 127;
    const int h   = pr >> 4;       // 0..7
    const int il  = pr & 15;       // 0..15
    const int irow = b * LL + i0 + il;

    // stage Ek/Ev (padded stride 33 -> conflict-free gather)
    for (int t = tid; t < RELN * 32; t += 256) {
        int r = t >> 5, d = t & 31;
        Eks[r * 33 + d] = Ek[t];
        Evs[r * 33 + d] = Ev[t];
    }

    float ql[32];
    {
        const float4* qp = (const float4*)(Q + (size_t)irow * HH + h * DHEAD);
#pragma unroll
        for (int d4 = 0; d4 < 8; d4++) {
            float4 v4 = qp[d4];
            ql[d4 * 4 + 0] = v4.x; ql[d4 * 4 + 1] = v4.y;
            ql[d4 * 4 + 2] = v4.z; ql[d4 * 4 + 3] = v4.w;
        }
    }

    float m = -INFINITY, s = 0.f;
    float oc[32];
#pragma unroll
    for (int d = 0; d < 32; d++) oc[d] = 0.f;

    const int NT = (LL / 2) / TJA;   // 32 tiles per half
    const float4* kg = (const float4*)Kk;
    const float4* vg = (const float4*)V;

    for (int t = 0; t < NT; t++) {
        __syncthreads();
        // stage K/V tiles for both halves (coalesced float4)
#pragma unroll
        for (int q4 = 0; q4 < 8; q4++) {
            int f  = tid + q4 * 256;            // 0..2047 float4 slots
            int fh = f >> 10;
            int jj = (f >> 6) & 15;
            int c4 = f & 63;
            int j  = fh * (LL / 2) + t * TJA + jj;
            int gi = (b * LL + j) * 64 + c4;
            ((float4*)Kt)[fh * 1024 + jj * 64 + c4] = kg[gi];
            ((float4*)Vt)[fh * 1024 + jj * 64 + c4] = vg[gi];
        }
        // stage relation idx + mask (mask is int32: bool -> int32 in harness)
#pragma unroll
        for (int q2 = 0; q2 < 2; q2++) {
            int f  = tid + q2 * 256;            // 0..511
            int fh = f >> 8, ii = (f >> 4) & 15, jj = f & 15;
            int j  = fh * (LL / 2) + t * TJA + jj;
            size_t gi = (size_t)(b * LL + i0 + ii) * LL + j;
            ri[fh * 256 + ii * 16 + jj] = rel[gi];
            mk[fh * 256 + ii * 16 + jj] = relmask[gi];
        }
        __syncthreads();

        const float* Kth = Kt + hf * (16 * 256);
        const float* Vth = Vt + hf * (16 * 256);
        const int* rih = ri + hf * 256 + il * 16;
        const int* mkh = mk + hf * 256 + il * 16;

#pragma unroll
        for (int jj = 0; jj < TJA; jj++) {
            int r = rih[jj];
            const float* kr  = Kth + jj * 256 + h * 32;
            const float* er  = Eks + r * 33;
            float dot = 0.f;
#pragma unroll
            for (int d = 0; d < 32; d++) dot += ql[d] * (kr[d] + er[d]);
            float e = dot * INV_SCALE;
            if (mkh[jj]) e -= 1e20f;
            float p;
            if (e > m) {
                float c = __expf(m - e);
                s *= c;
#pragma unroll
                for (int d = 0; d < 32; d++) oc[d] *= c;
                m = e;
                p = 1.f;
            } else {
                p = __expf(e - m);
            }
            s += p;
            const float* vr  = Vth + jj * 256 + h * 32;
            const float* evr = Evs + r * 33;
#pragma unroll
            for (int d = 0; d < 32; d++) oc[d] += p * (vr[d] + evr[d]);
        }
    }

    // combine the two j-halves (reuse Kt region)
    __syncthreads();
    float* cm = Kt;             // 128
    float* cs = Kt + 128;       // 128
    float* co = Kt + 256;       // 128*32
    if (hf == 1) {
        cm[pr] = m; cs[pr] = s;
#pragma unroll
        for (int d = 0; d < 32; d++) co[pr * 32 + d] = oc[d];
    }
    __syncthreads();
    if (hf == 0) {
        float m2 = cm[pr], s2 = cs[pr];
        float nm = fmaxf(m, m2);
        float c1 = __expf(m - nm), c2 = __expf(m2 - nm);
        float inv = 1.f / (s * c1 + s2 * c2);
        float* op = O + (size_t)irow * HH + h * 32;
#pragma unroll
        for (int d = 0; d < 32; d++)
            op[d] = (oc[d] * c1 + co[pr * 32 + d] * c2) * inv;
    }
}

// ------------------------------------------------- Residual + LayerNorm ----
__global__ __launch_bounds__(256) void ln_kernel(
    const float* __restrict__ X, const float* __restrict__ Y,
    const float* __restrict__ g, const float* __restrict__ bta,
    float* __restrict__ Out)
{
    const int r = blockIdx.x;
    const int c = threadIdx.x;
    float v = X[(size_t)r * HH + c] + Y[(size_t)r * HH + c];
    float s1 = v, s2 = v * v;
#pragma unroll
    for (int o = 16; o; o >>= 1) {
        s1 += __shfl_xor_sync(0xffffffffu, s1, o);
        s2 += __shfl_xor_sync(0xffffffffu, s2, o);
    }
    __shared__ float r1[8], r2[8];
    if ((c & 31) == 0) { r1[c >> 5] = s1; r2[c >> 5] = s2; }
    __syncthreads();
    if (c < 32) {
        s1 = (c < 8) ? r1[c] : 0.f;
        s2 = (c < 8) ? r2[c] : 0.f;
#pragma unroll
        for (int o = 4; o; o >>= 1) {
            s1 += __shfl_xor_sync(0xffffffffu, s1, o);
            s2 += __shfl_xor_sync(0xffffffffu, s2, o);
        }
        if (c == 0) { r1[0] = s1; r2[0] = s2; }
    }
    __syncthreads();
    float mean = r1[0] * (1.f / HH);
    float var  = r2[0] * (1.f / HH) - mean * mean;
    Out[(size_t)r * HH + c] = (v - mean) * rsqrtf(var + EPSLN) * g[c] + bta[c];
}

// ------------------------------------------------------------- launcher ----
extern "C" void kernel_launch(void* const* d_in, const int* in_sizes, int n_in,
                              void* d_out, int out_size)
{
    const float* inputs = (const float*)d_in[0];
    const float* Wq  = (const float*)d_in[1];
    const float* Wk  = (const float*)d_in[2];
    const float* Wv  = (const float*)d_in[3];
    const float* Wo  = (const float*)d_in[4];
    const float* bo  = (const float*)d_in[5];
    const float* W1  = (const float*)d_in[6];
    const float* b1  = (const float*)d_in[7];
    const float* W2  = (const float*)d_in[8];
    const float* b2  = (const float*)d_in[9];
    const float* ln1g = (const float*)d_in[10];
    const float* ln1b = (const float*)d_in[11];
    const float* ln2g = (const float*)d_in[12];
    const float* ln2b = (const float*)d_in[13];
    const float* Ek  = (const float*)d_in[14];
    const float* Ev  = (const float*)d_in[15];
    const int*   rel = (const int*)d_in[16];
    const int*   rmask = (const int*)d_in[17];
    float* out = (float*)d_out;

    float *qb, *kb, *vb, *ab, *yb, *xb, *fb;
    cudaGetSymbolAddress((void**)&qb, g_qb);
    cudaGetSymbolAddress((void**)&kb, g_kb);
    cudaGetSymbolAddress((void**)&vb, g_vb);
    cudaGetSymbolAddress((void**)&ab, g_ab);
    cudaGetSymbolAddress((void**)&yb, g_yb);
    cudaGetSymbolAddress((void**)&xb, g_xb);
    cudaGetSymbolAddress((void**)&fb, g_fb);

    cudaFuncSetAttribute(attn_kernel,
                         cudaFuncAttributeMaxDynamicSharedMemorySize,
                         ATTN_SMEM_BYTES);

    for (int l = 0; l < NLAYER; l++) {
        const float* x = (l == 0) ? inputs : xb;
        const size_t wHH = (size_t)l * HH * HH;
        const size_t wHF = (size_t)l * HH * FFD;

        gemm_kernel<<<dim3(HH/64, ROWS/64), 256>>>(x, Wq + wHH, nullptr, qb, ROWS, HH, HH, 0);
        gemm_kernel<<<dim3(HH/64, ROWS/64), 256>>>(x, Wk + wHH, nullptr, kb, ROWS, HH, HH, 0);
        gemm_kernel<<<dim3(HH/64, ROWS/64), 256>>>(x, Wv + wHH, nullptr, vb, ROWS, HH, HH, 0);

        attn_kernel<<<dim3(LL/TI, BB), 256, ATTN_SMEM_BYTES>>>(qb, kb, vb, Ek, Ev, rel, rmask, ab);

        gemm_kernel<<<dim3(HH/64, ROWS/64), 256>>>(ab, Wo + wHH, bo + l*HH, yb, ROWS, HH, HH, 0);
        ln_kernel<<<ROWS, HH>>>(x, yb, ln1g + l*HH, ln1b + l*HH, xb);

        gemm_kernel<<<dim3(FFD/64, ROWS/64), 256>>>(xb, W1 + wHF, b1 + l*FFD, fb, ROWS, FFD, HH, 1);
        gemm_kernel<<<dim3(HH/64, ROWS/64), 256>>>(fb, W2 + wHF, b2 + l*HH, yb, ROWS, HH, FFD, 0);
        ln_kernel<<<ROWS, HH>>>(xb, yb, ln2g + l*HH, ln2b + l*HH, (l == NLAYER-1) ? out : xb);
    }
}

// round 3
// speedup vs baseline: 1.3726x; 1.3726x over previous
#include <cuda_runtime.h>
#include <math.h>

// Problem constants
#define BB 2
#define LL 1024
#define HH 256
#define NHEAD 8
#define DHEAD 32
#define FFD 1024
#define NLAYER 2
#define RELN 100
#define EPSLN 1e-5f
// 1/sqrt(32) * log2(e)  (exp done in base 2)
#define QSCALE (0.17677669529663687f * 1.4426950408889634f)

#define ROWS (BB*LL)          // 2048

// ---------------- scratch (static device memory; no allocations allowed) ----
__device__ float g_qb[ROWS*HH];
__device__ float g_kb[ROWS*HH];
__device__ float g_vb[ROWS*HH];
__device__ float g_ab[ROWS*HH];
__device__ float g_yb[ROWS*HH];
__device__ float g_xb[ROWS*HH];
__device__ float g_fb[ROWS*FFD];

__device__ __forceinline__ float ex2f(float x) {
    float y;
    asm("ex2.approx.ftz.f32 %0, %1;" : "=f"(y) : "f"(x));
    return y;
}

// ---------------------------------------------------------------- GEMM -----
// C[M,N] = A[M,K] @ B[K,N] (+bias) (+relu). 64x64 tile, TK=16, 256 thr, 4x4.
__device__ __forceinline__ void gemm_body(
    const float* __restrict__ A, const float* __restrict__ B,
    const float* __restrict__ bias, float* __restrict__ C,
    int N, int K, int doRelu, int bm, int bn)
{
    __shared__ float As[16][68];   // [k][m] transposed, padded
    __shared__ float Bs[16][68];   // [k][n], padded

    const int tid = threadIdx.x;
    const int tx = tid & 15;        // 0..15 -> n
    const int ty = tid >> 4;        // 0..15 -> m

    const int arow = tid >> 2;          // 0..63
    const int acol = (tid & 3) * 4;     // 0,4,8,12
    const int brow = tid >> 4;          // 0..15
    const int bcol = (tid & 15) * 4;    // 0..60

    float acc[4][4];
#pragma unroll
    for (int i = 0; i < 4; i++)
#pragma unroll
        for (int j = 0; j < 4; j++) acc[i][j] = 0.f;

    for (int k0 = 0; k0 < K; k0 += 16) {
        float4 av = *(const float4*)(A + (size_t)(bm + arow) * K + k0 + acol);
        As[acol + 0][arow] = av.x;
        As[acol + 1][arow] = av.y;
        As[acol + 2][arow] = av.z;
        As[acol + 3][arow] = av.w;
        float4 bv = *(const float4*)(B + (size_t)(k0 + brow) * N + bn + bcol);
        *(float4*)&Bs[brow][bcol] = bv;
        __syncthreads();
#pragma unroll
        for (int k = 0; k < 16; k++) {
            float a0 = As[k][ty * 4 + 0];
            float a1 = As[k][ty * 4 + 1];
            float a2 = As[k][ty * 4 + 2];
            float a3 = As[k][ty * 4 + 3];
            float4 b4 = *(const float4*)&Bs[k][tx * 4];
            acc[0][0] += a0 * b4.x; acc[0][1] += a0 * b4.y; acc[0][2] += a0 * b4.z; acc[0][3] += a0 * b4.w;
            acc[1][0] += a1 * b4.x; acc[1][1] += a1 * b4.y; acc[1][2] += a1 * b4.z; acc[1][3] += a1 * b4.w;
            acc[2][0] += a2 * b4.x; acc[2][1] += a2 * b4.y; acc[2][2] += a2 * b4.z; acc[2][3] += a2 * b4.w;
            acc[3][0] += a3 * b4.x; acc[3][1] += a3 * b4.y; acc[3][2] += a3 * b4.z; acc[3][3] += a3 * b4.w;
        }
        __syncthreads();
    }

    float bb0 = 0.f, bb1 = 0.f, bb2 = 0.f, bb3 = 0.f;
    if (bias) {
        const float4 b4 = *(const float4*)(bias + bn + tx * 4);
        bb0 = b4.x; bb1 = b4.y; bb2 = b4.z; bb3 = b4.w;
    }
#pragma unroll
    for (int i = 0; i < 4; i++) {
        float4 o;
        o.x = acc[i][0] + bb0;
        o.y = acc[i][1] + bb1;
        o.z = acc[i][2] + bb2;
        o.w = acc[i][3] + bb3;
        if (doRelu) {
            o.x = fmaxf(o.x, 0.f); o.y = fmaxf(o.y, 0.f);
            o.z = fmaxf(o.z, 0.f); o.w = fmaxf(o.w, 0.f);
        }
        *(float4*)(C + (size_t)(bm + ty * 4 + i) * N + bn + tx * 4) = o;
    }
}

__global__ __launch_bounds__(256) void gemm_kernel(
    const float* __restrict__ A, const float* __restrict__ B,
    const float* __restrict__ bias, float* __restrict__ C,
    int M, int N, int K, int doRelu)
{
    gemm_body(A, B, bias, C, N, K, doRelu, blockIdx.y * 64, blockIdx.x * 64);
}

// fused QKV: blockIdx.z selects which weight/output
__global__ __launch_bounds__(256) void gemm_qkv_kernel(
    const float* __restrict__ A,
    const float* __restrict__ Bq, const float* __restrict__ Bk,
    const float* __restrict__ Bv,
    float* __restrict__ Cq, float* __restrict__ Ck, float* __restrict__ Cv)
{
    const float* B = (blockIdx.z == 0) ? Bq : (blockIdx.z == 1) ? Bk : Bv;
    float*       C = (blockIdx.z == 0) ? Cq : (blockIdx.z == 1) ? Ck : Cv;
    gemm_body(A, B, nullptr, C, HH, HH, 0, blockIdx.y * 64, blockIdx.x * 64);
}

// ----------------------------------------------------------- Attention -----
// Block: 16 query rows x 8 heads x one batch. 256 threads:
//   hf = tid>>7 : j-half (split-K over j in [hf*512, hf*512+512))
//   pr = tid&127: h = pr>>4, il = pr&15
// qrel[i,h,r] = q_scaled . Ek[r] precomputed (kills Ek gather)
// w[r] histogram of softmax mass per relation (kills Ev gather)
#define TI 16
#define TJA 16

// smem float offsets
#define SM_QREL 0                       // 128*101 = 12928
#define SM_KT   12928                   // 2*16*256 = 8192
#define SM_VT   21120                   // 8192
#define SM_W    29312                   // 256*101 = 25856
#define SM_RI   55168                   // 512 ints
#define SM_MK   55680                   // 512 ints
#define ATTN_SMEM_FLOATS 56192
#define ATTN_SMEM_BYTES  (ATTN_SMEM_FLOATS*4)   // 224768 B

__global__ __launch_bounds__(256, 1) void attn_kernel(
    const float* __restrict__ Q, const float* __restrict__ Kk,
    const float* __restrict__ V, const float* __restrict__ Ek,
    const float* __restrict__ Ev, const int* __restrict__ rel,
    const int* __restrict__ relmask, float* __restrict__ O)
{
    extern __shared__ float sm[];
    float* QREL = sm + SM_QREL;              // [128][101]
    float* Kt   = sm + SM_KT;                // [2][16][256]
    float* Vt   = sm + SM_VT;
    float* Wh   = sm + SM_W;                 // [256][101]
    int*   ri   = (int*)(sm + SM_RI);        // [2][16][16]
    int*   mk   = (int*)(sm + SM_MK);

    const int tid = threadIdx.x;
    const int b   = blockIdx.y;
    const int i0  = blockIdx.x * TI;
    const int hf  = tid >> 7;
    const int pr  = tid & 127;
    const int h   = pr >> 4;       // 0..7
    const int il  = pr & 15;       // 0..15
    const int irow = b * LL + i0 + il;

    // q (pre-scaled by 1/sqrt(d)*log2e)
    float ql[32];
    {
        const float4* qp = (const float4*)(Q + (size_t)irow * HH + h * DHEAD);
#pragma unroll
        for (int d4 = 0; d4 < 8; d4++) {
            float4 v4 = qp[d4];
            ql[d4 * 4 + 0] = v4.x * QSCALE; ql[d4 * 4 + 1] = v4.y * QSCALE;
            ql[d4 * 4 + 2] = v4.z * QSCALE; ql[d4 * 4 + 3] = v4.w * QSCALE;
        }
    }

    // qrel precompute: row pr, this half's r range
    {
        float* qrow = QREL + pr * 101;
#pragma unroll 2
        for (int r = hf * 50; r < hf * 50 + 50; r++) {
            const float4* e4 = (const float4*)(Ek + r * 32);
            float d0 = 0.f, d1 = 0.f, d2 = 0.f, d3 = 0.f;
#pragma unroll
            for (int d4 = 0; d4 < 8; d4++) {
                float4 ev = e4[d4];
                d0 += ql[d4 * 4 + 0] * ev.x;
                d1 += ql[d4 * 4 + 1] * ev.y;
                d2 += ql[d4 * 4 + 2] * ev.z;
                d3 += ql[d4 * 4 + 3] * ev.w;
            }
            qrow[r] = (d0 + d1) + (d2 + d3);
        }
    }

    // zero this thread's w histogram
    float* wr = Wh + tid * 101;
#pragma unroll 1
    for (int r = 0; r < RELN; r++) wr[r] = 0.f;

    float m = -INFINITY, s = 0.f;
    float oc[32];
#pragma unroll
    for (int d = 0; d < 32; d++) oc[d] = 0.f;

    const int NT = (LL / 2) / TJA;   // 32 tiles per half
    const float4* kg = (const float4*)Kk;
    const float4* vg = (const float4*)V;
    const float* qrow = QREL + pr * 101;

    for (int t = 0; t < NT; t++) {
        __syncthreads();
        // stage K/V tiles for both halves (coalesced float4)
#pragma unroll
        for (int q4 = 0; q4 < 8; q4++) {
            int f  = tid + q4 * 256;            // 0..2047 float4 slots
            int fh = f >> 10;
            int jj = (f >> 6) & 15;
            int c4 = f & 63;
            int j  = fh * (LL / 2) + t * TJA + jj;
            int gi = (b * LL + j) * 64 + c4;
            ((float4*)Kt)[fh * 1024 + jj * 64 + c4] = kg[gi];
            ((float4*)Vt)[fh * 1024 + jj * 64 + c4] = vg[gi];
        }
        // stage relation idx + mask (int32)
#pragma unroll
        for (int q2 = 0; q2 < 2; q2++) {
            int f  = tid + q2 * 256;            // 0..511
            int fh = f >> 8, ii = (f >> 4) & 15, jj = f & 15;
            int j  = fh * (LL / 2) + t * TJA + jj;
            size_t gi = (size_t)(b * LL + i0 + ii) * LL + j;
            ri[fh * 256 + ii * 16 + jj] = rel[gi];
            mk[fh * 256 + ii * 16 + jj] = relmask[gi];
        }
        __syncthreads();

        const float* Kth = Kt + hf * (16 * 256);
        const float* Vth = Vt + hf * (16 * 256);
        const int* rih = ri + hf * 256 + il * 16;
        const int* mkh = mk + hf * 256 + il * 16;

        // pass 1: scores + tile max
        float e[TJA];
        float tmax = -INFINITY;
#pragma unroll 4
        for (int jj = 0; jj < TJA; jj++) {
            const float4* kr4 = (const float4*)(Kth + jj * 256 + h * 32);
            float d0 = 0.f, d1 = 0.f, d2 = 0.f, d3 = 0.f;
#pragma unroll
            for (int d4 = 0; d4 < 8; d4++) {
                float4 kv = kr4[d4];
                d0 += ql[d4 * 4 + 0] * kv.x;
                d1 += ql[d4 * 4 + 1] * kv.y;
                d2 += ql[d4 * 4 + 2] * kv.z;
                d3 += ql[d4 * 4 + 3] * kv.w;
            }
            int r = rih[jj];
            float ee = (d0 + d1) + (d2 + d3) + qrow[r];
            ee = mkh[jj] ? -1e30f : ee;
            e[jj] = ee;
            tmax = fmaxf(tmax, ee);
        }

        // single rescale per tile (rare after warm-up)
        if (tmax > m) {
            float c = ex2f(m - tmax);
            s *= c;
#pragma unroll
            for (int d = 0; d < 32; d++) oc[d] *= c;
#pragma unroll 1
            for (int r = 0; r < RELN; r++) wr[r] *= c;
            m = tmax;
        }

        // pass 2: accumulate
#pragma unroll 4
        for (int jj = 0; jj < TJA; jj++) {
            float p = ex2f(e[jj] - m);
            s += p;
            wr[rih[jj]] += p;
            const float4* vr4 = (const float4*)(Vth + jj * 256 + h * 32);
#pragma unroll
            for (int d4 = 0; d4 < 8; d4++) {
                float4 vv = vr4[d4];
                oc[d4 * 4 + 0] += p * vv.x;
                oc[d4 * 4 + 1] += p * vv.y;
                oc[d4 * 4 + 2] += p * vv.z;
                oc[d4 * 4 + 3] += p * vv.w;
            }
        }
    }

    // ---- combine the two halves; add relation-value term; write out ----
    __syncthreads();
    float* cm  = Kt;               // 128
    float* cs  = Kt + 128;         // 128
    float* co  = Kt + 256;         // 128*32
    float* Evs = Vt;               // 3200 floats staged Ev

    for (int t2 = tid; t2 < RELN * 32; t2 += 256) Evs[t2] = Ev[t2];

    if (hf == 1) {
        cm[pr] = m; cs[pr] = s;
#pragma unroll
        for (int d4 = 0; d4 < 8; d4++) {
            float4 v4;
            v4.x = oc[d4 * 4 + 0]; v4.y = oc[d4 * 4 + 1];
            v4.z = oc[d4 * 4 + 2]; v4.w = oc[d4 * 4 + 3];
            *(float4*)(co + pr * 32 + d4 * 4) = v4;
        }
    }
    __syncthreads();
    if (hf == 0) {
        float m2 = cm[pr], s2 = cs[pr];
        float nm = fmaxf(m, m2);
        float c1 = ex2f(m - nm), c2 = ex2f(m2 - nm);
        float inv = 1.f / (s * c1 + s2 * c2);

        float of[32];
#pragma unroll
        for (int d4 = 0; d4 < 8; d4++) {
            float4 o2 = *(const float4*)(co + pr * 32 + d4 * 4);
            of[d4 * 4 + 0] = oc[d4 * 4 + 0] * c1 + o2.x * c2;
            of[d4 * 4 + 1] = oc[d4 * 4 + 1] * c1 + o2.y * c2;
            of[d4 * 4 + 2] = oc[d4 * 4 + 2] * c1 + o2.z * c2;
            of[d4 * 4 + 3] = oc[d4 * 4 + 3] * c1 + o2.w * c2;
        }

        const float* w0 = Wh + pr * 101;
        const float* w1 = Wh + (128 + pr) * 101;
#pragma unroll 2
        for (int r = 0; r < RELN; r++) {
            float wv = w0[r] * c1 + w1[r] * c2;
            const float4* ev4 = (const float4*)(Evs + r * 32);
#pragma unroll
            for (int d4 = 0; d4 < 8; d4++) {
                float4 ev = ev4[d4];
                of[d4 * 4 + 0] += wv * ev.x;
                of[d4 * 4 + 1] += wv * ev.y;
                of[d4 * 4 + 2] += wv * ev.z;
                of[d4 * 4 + 3] += wv * ev.w;
            }
        }

        float* op = O + (size_t)irow * HH + h * 32;
#pragma unroll
        for (int d4 = 0; d4 < 8; d4++) {
            float4 v4;
            v4.x = of[d4 * 4 + 0] * inv; v4.y = of[d4 * 4 + 1] * inv;
            v4.z = of[d4 * 4 + 2] * inv; v4.w = of[d4 * 4 + 3] * inv;
            *(float4*)(op + d4 * 4) = v4;
        }
    }
}

// ------------------------------------------------- Residual + LayerNorm ----
__global__ __launch_bounds__(256) void ln_kernel(
    const float* __restrict__ X, const float* __restrict__ Y,
    const float* __restrict__ g, const float* __restrict__ bta,
    float* __restrict__ Out)
{
    const int r = blockIdx.x;
    const int c = threadIdx.x;
    float v = X[(size_t)r * HH + c] + Y[(size_t)r * HH + c];
    float s1 = v, s2 = v * v;
#pragma unroll
    for (int o = 16; o; o >>= 1) {
        s1 += __shfl_xor_sync(0xffffffffu, s1, o);
        s2 += __shfl_xor_sync(0xffffffffu, s2, o);
    }
    __shared__ float r1[8], r2[8];
    if ((c & 31) == 0) { r1[c >> 5] = s1; r2[c >> 5] = s2; }
    __syncthreads();
    if (c < 32) {
        s1 = (c < 8) ? r1[c] : 0.f;
        s2 = (c < 8) ? r2[c] : 0.f;
#pragma unroll
        for (int o = 4; o; o >>= 1) {
            s1 += __shfl_xor_sync(0xffffffffu, s1, o);
            s2 += __shfl_xor_sync(0xffffffffu, s2, o);
        }
        if (c == 0) { r1[0] = s1; r2[0] = s2; }
    }
    __syncthreads();
    float mean = r1[0] * (1.f / HH);
    float var  = r2[0] * (1.f / HH) - mean * mean;
    Out[(size_t)r * HH + c] = (v - mean) * rsqrtf(var + EPSLN) * g[c] + bta[c];
}

// ------------------------------------------------------------- launcher ----
extern "C" void kernel_launch(void* const* d_in, const int* in_sizes, int n_in,
                              void* d_out, int out_size)
{
    const float* inputs = (const float*)d_in[0];
    const float* Wq  = (const float*)d_in[1];
    const float* Wk  = (const float*)d_in[2];
    const float* Wv  = (const float*)d_in[3];
    const float* Wo  = (const float*)d_in[4];
    const float* bo  = (const float*)d_in[5];
    const float* W1  = (const float*)d_in[6];
    const float* b1  = (const float*)d_in[7];
    const float* W2  = (const float*)d_in[8];
    const float* b2  = (const float*)d_in[9];
    const float* ln1g = (const float*)d_in[10];
    const float* ln1b = (const float*)d_in[11];
    const float* ln2g = (const float*)d_in[12];
    const float* ln2b = (const float*)d_in[13];
    const float* Ek  = (const float*)d_in[14];
    const float* Ev  = (const float*)d_in[15];
    const int*   rel = (const int*)d_in[16];
    const int*   rmask = (const int*)d_in[17];
    float* out = (float*)d_out;

    float *qb, *kb, *vb, *ab, *yb, *xb, *fb;
    cudaGetSymbolAddress((void**)&qb, g_qb);
    cudaGetSymbolAddress((void**)&kb, g_kb);
    cudaGetSymbolAddress((void**)&vb, g_vb);
    cudaGetSymbolAddress((void**)&ab, g_ab);
    cudaGetSymbolAddress((void**)&yb, g_yb);
    cudaGetSymbolAddress((void**)&xb, g_xb);
    cudaGetSymbolAddress((void**)&fb, g_fb);

    cudaFuncSetAttribute(attn_kernel,
                         cudaFuncAttributeMaxDynamicSharedMemorySize,
                         ATTN_SMEM_BYTES);

    for (int l = 0; l < NLAYER; l++) {
        const float* x = (l == 0) ? inputs : xb;
        const size_t wHH = (size_t)l * HH * HH;
        const size_t wHF = (size_t)l * HH * FFD;

        gemm_qkv_kernel<<<dim3(HH/64, ROWS/64, 3), 256>>>(
            x, Wq + wHH, Wk + wHH, Wv + wHH, qb, kb, vb);

        attn_kernel<<<dim3(LL/TI, BB), 256, ATTN_SMEM_BYTES>>>(qb, kb, vb, Ek, Ev, rel, rmask, ab);

        gemm_kernel<<<dim3(HH/64, ROWS/64), 256>>>(ab, Wo + wHH, bo + l*HH, yb, ROWS, HH, HH, 0);
        ln_kernel<<<ROWS, HH>>>(x, yb, ln1g + l*HH, ln1b + l*HH, xb);

        gemm_kernel<<<dim3(FFD/64, ROWS/64), 256>>>(xb, W1 + wHF, b1 + l*FFD, fb, ROWS, FFD, HH, 1);
        gemm_kernel<<<dim3(HH/64, ROWS/64), 256>>>(fb, W2 + wHF, b2 + l*HH, yb, ROWS, HH, FFD, 0);
        ln_kernel<<<ROWS, HH>>>(xb, yb, ln2g + l*HH, ln2b + l*HH, (l == NLAYER-1) ? out : xb);
    }
}

// round 4
// speedup vs baseline: 1.5384x; 1.1208x over previous
#include <cuda_runtime.h>
#include <math.h>
#include <stdint.h>

// Problem constants
#define BB 2
#define LL 1024
#define HH 256
#define NHEAD 8
#define DHEAD 32
#define FFD 1024
#define NLAYER 2
#define RELN 100
#define EPSLN 1e-5f
// 1/sqrt(32) * log2(e)  (exp done in base 2)
#define QSCALE (0.17677669529663687f * 1.4426950408889634f)

#define ROWS (BB*LL)          // 2048

// ---------------- scratch (static device memory; no allocations allowed) ----
__device__ float g_qb[ROWS*HH];
__device__ float g_kb[ROWS*HH];
__device__ float g_vb[ROWS*HH];
__device__ float g_ab[ROWS*HH];
__device__ float g_yb[ROWS*HH];
__device__ float g_xb[ROWS*HH];
__device__ float g_fb[ROWS*FFD];

__device__ __forceinline__ float ex2f(float x) {
    float y;
    asm("ex2.approx.ftz.f32 %0, %1;" : "=f"(y) : "f"(x));
    return y;
}

__device__ __forceinline__ float tf32r(float x) {
    float y;
    asm("cvt.rna.tf32.f32 %0, %1;" : "=f"(y) : "f"(x));
    return y;
}

// ------------------------------------------------------- tf32 MMA GEMM -----
// C[M,N] = A[M,K] @ B[K,N] (+bias)(+relu). Tile 64x64, BK=32, 256 thr.
// 8 warps: 4 along M (16 rows each) x 2 along N (32 cols each).
// mma.sync.m16n8k8.tf32: per warp per k8-step: 1 A frag, 4 B frags, 4 mma.
#define BM 64
#define BN 64
#define BKG 32
#define APAD 8
#define BPAD 8

__device__ __forceinline__ void mma_tf32(
    float& c0, float& c1, float& c2, float& c3,
    uint32_t a0, uint32_t a1, uint32_t a2, uint32_t a3,
    uint32_t b0, uint32_t b1)
{
    asm volatile(
        "mma.sync.aligned.m16n8k8.row.col.f32.tf32.tf32.f32 "
        "{%0,%1,%2,%3}, {%4,%5,%6,%7}, {%8,%9}, {%0,%1,%2,%3};"
        : "+f"(c0), "+f"(c1), "+f"(c2), "+f"(c3)
        : "r"(a0), "r"(a1), "r"(a2), "r"(a3), "r"(b0), "r"(b1));
}

__device__ __forceinline__ void gemm_tf32_body(
    const float* __restrict__ A, const float* __restrict__ B,
    const float* __restrict__ bias, float* __restrict__ C,
    int N, int K, int doRelu, int bm, int bn)
{
    __shared__ float As[BKG][BM + APAD];   // [k][m]
    __shared__ float Bs[BKG][BN + BPAD];   // [k][n]

    const int tid  = threadIdx.x;
    const int warp = tid >> 5;
    const int lane = tid & 31;
    const int wm = (warp & 3) * 16;        // warp m offset
    const int wn = (warp >> 2) * 32;       // warp n offset
    const int g  = lane >> 2;              // group id 0..7
    const int tg = lane & 3;               // thread-in-group 0..3

    float acc[4][4];
#pragma unroll
    for (int i = 0; i < 4; i++)
#pragma unroll
        for (int j = 0; j < 4; j++) acc[i][j] = 0.f;

    // staging coords (2 float4 each for A and B per chunk)
    const int ar0 = tid >> 3;              // A: rows 0..31 (f=tid), 32..63 (f=tid+256)
    const int ac0 = (tid & 7) * 4;
    const int br0 = tid >> 4;              // B: rows 0..15, 16..31
    const int bc0 = (tid & 15) * 4;

    for (int k0 = 0; k0 < K; k0 += BKG) {
#pragma unroll
        for (int it = 0; it < 2; it++) {
            int arow = ar0 + it * 32;
            float4 av = *(const float4*)(A + (size_t)(bm + arow) * K + k0 + ac0);
            As[ac0 + 0][arow] = tf32r(av.x);
            As[ac0 + 1][arow] = tf32r(av.y);
            As[ac0 + 2][arow] = tf32r(av.z);
            As[ac0 + 3][arow] = tf32r(av.w);
            int brow = br0 + it * 16;
            float4 bv = *(const float4*)(B + (size_t)(k0 + brow) * N + bn + bc0);
            float4 bc;
            bc.x = tf32r(bv.x); bc.y = tf32r(bv.y);
            bc.z = tf32r(bv.z); bc.w = tf32r(bv.w);
            *(float4*)&Bs[brow][bc0] = bc;
        }
        __syncthreads();

#pragma unroll
        for (int ks = 0; ks < BKG; ks += 8) {
            uint32_t a0 = __float_as_uint(As[ks + tg    ][wm + g    ]);
            uint32_t a1 = __float_as_uint(As[ks + tg    ][wm + g + 8]);
            uint32_t a2 = __float_as_uint(As[ks + tg + 4][wm + g    ]);
            uint32_t a3 = __float_as_uint(As[ks + tg + 4][wm + g + 8]);
#pragma unroll
            for (int nt = 0; nt < 4; nt++) {
                uint32_t b0 = __float_as_uint(Bs[ks + tg    ][wn + nt * 8 + g]);
                uint32_t b1 = __float_as_uint(Bs[ks + tg + 4][wn + nt * 8 + g]);
                mma_tf32(acc[nt][0], acc[nt][1], acc[nt][2], acc[nt][3],
                         a0, a1, a2, a3, b0, b1);
            }
        }
        __syncthreads();
    }

    // epilogue: c0,c1 -> (row0, col..col+1); c2,c3 -> (row0+8, ...)
    const int row0 = bm + wm + g;
    const int colb = bn + wn + 2 * tg;
#pragma unroll
    for (int nt = 0; nt < 4; nt++) {
        int col = colb + nt * 8;
        float b0v = 0.f, b1v = 0.f;
        if (bias) { b0v = bias[col]; b1v = bias[col + 1]; }
        float2 o0, o1;
        o0.x = acc[nt][0] + b0v; o0.y = acc[nt][1] + b1v;
        o1.x = acc[nt][2] + b0v; o1.y = acc[nt][3] + b1v;
        if (doRelu) {
            o0.x = fmaxf(o0.x, 0.f); o0.y = fmaxf(o0.y, 0.f);
            o1.x = fmaxf(o1.x, 0.f); o1.y = fmaxf(o1.y, 0.f);
        }
        *(float2*)(C + (size_t)row0 * N + col)       = o0;
        *(float2*)(C + (size_t)(row0 + 8) * N + col) = o1;
    }
}

__global__ __launch_bounds__(256) void gemm_kernel(
    const float* __restrict__ A, const float* __restrict__ B,
    const float* __restrict__ bias, float* __restrict__ C,
    int N, int K, int doRelu)
{
    gemm_tf32_body(A, B, bias, C, N, K, doRelu, blockIdx.y * BM, blockIdx.x * BN);
}

// fused QKV: blockIdx.z selects which weight/output
__global__ __launch_bounds__(256) void gemm_qkv_kernel(
    const float* __restrict__ A,
    const float* __restrict__ Bq, const float* __restrict__ Bk,
    const float* __restrict__ Bv,
    float* __restrict__ Cq, float* __restrict__ Ck, float* __restrict__ Cv)
{
    const float* B = (blockIdx.z == 0) ? Bq : (blockIdx.z == 1) ? Bk : Bv;
    float*       C = (blockIdx.z == 0) ? Cq : (blockIdx.z == 1) ? Ck : Cv;
    gemm_tf32_body(A, B, nullptr, C, HH, HH, 0, blockIdx.y * BM, blockIdx.x * BN);
}

// ----------------------------------------------------------- Attention -----
// Block: 16 query rows x 8 heads x one batch. 256 threads:
//   hf = tid>>7 : j-half (split-K over j in [hf*512, hf*512+512))
//   pr = tid&127: h = pr>>4, il = pr&15
// qrel[i,h,r] = q_scaled . Ek[r] precomputed (kills Ek gather)
// w[r] histogram of softmax mass per relation (kills Ev gather)
#define TI 16
#define TJA 16

// smem float offsets
#define SM_QREL 0                       // 128*101 = 12928
#define SM_KT   12928                   // 2*16*256 = 8192
#define SM_VT   21120                   // 8192
#define SM_W    29312                   // 256*101 = 25856
#define SM_RI   55168                   // 512 ints
#define SM_MK   55680                   // 512 ints
#define ATTN_SMEM_FLOATS 56192
#define ATTN_SMEM_BYTES  (ATTN_SMEM_FLOATS*4)   // 224768 B

__global__ __launch_bounds__(256, 1) void attn_kernel(
    const float* __restrict__ Q, const float* __restrict__ Kk,
    const float* __restrict__ V, const float* __restrict__ Ek,
    const float* __restrict__ Ev, const int* __restrict__ rel,
    const int* __restrict__ relmask, float* __restrict__ O)
{
    extern __shared__ float sm[];
    float* QREL = sm + SM_QREL;              // [128][101]
    float* Kt   = sm + SM_KT;                // [2][16][256]
    float* Vt   = sm + SM_VT;
    float* Wh   = sm + SM_W;                 // [256][101]
    int*   ri   = (int*)(sm + SM_RI);        // [2][16][16]
    int*   mk   = (int*)(sm + SM_MK);

    const int tid = threadIdx.x;
    const int b   = blockIdx.y;
    const int i0  = blockIdx.x * TI;
    const int hf  = tid >> 7;
    const int pr  = tid & 127;
    const int h   = pr >> 4;       // 0..7
    const int il  = pr & 15;       // 0..15
    const int irow = b * LL + i0 + il;

    // q (pre-scaled by 1/sqrt(d)*log2e)
    float ql[32];
    {
        const float4* qp = (const float4*)(Q + (size_t)irow * HH + h * DHEAD);
#pragma unroll
        for (int d4 = 0; d4 < 8; d4++) {
            float4 v4 = qp[d4];
            ql[d4 * 4 + 0] = v4.x * QSCALE; ql[d4 * 4 + 1] = v4.y * QSCALE;
            ql[d4 * 4 + 2] = v4.z * QSCALE; ql[d4 * 4 + 3] = v4.w * QSCALE;
        }
    }

    // qrel precompute: row pr, this half's r range
    {
        float* qrow = QREL + pr * 101;
#pragma unroll 2
        for (int r = hf * 50; r < hf * 50 + 50; r++) {
            const float4* e4 = (const float4*)(Ek + r * 32);
            float d0 = 0.f, d1 = 0.f, d2 = 0.f, d3 = 0.f;
#pragma unroll
            for (int d4 = 0; d4 < 8; d4++) {
                float4 ev = e4[d4];
                d0 += ql[d4 * 4 + 0] * ev.x;
                d1 += ql[d4 * 4 + 1] * ev.y;
                d2 += ql[d4 * 4 + 2] * ev.z;
                d3 += ql[d4 * 4 + 3] * ev.w;
            }
            qrow[r] = (d0 + d1) + (d2 + d3);
        }
    }

    // zero this thread's w histogram
    float* wr = Wh + tid * 101;
#pragma unroll 1
    for (int r = 0; r < RELN; r++) wr[r] = 0.f;

    float m = -INFINITY, s = 0.f;
    float oc[32];
#pragma unroll
    for (int d = 0; d < 32; d++) oc[d] = 0.f;

    const int NT = (LL / 2) / TJA;   // 32 tiles per half
    const float4* kg = (const float4*)Kk;
    const float4* vg = (const float4*)V;
    const float* qrow = QREL + pr * 101;

    for (int t = 0; t < NT; t++) {
        __syncthreads();
        // stage K/V tiles for both halves (coalesced float4)
#pragma unroll
        for (int q4 = 0; q4 < 8; q4++) {
            int f  = tid + q4 * 256;            // 0..2047 float4 slots
            int fh = f >> 10;
            int jj = (f >> 6) & 15;
            int c4 = f & 63;
            int j  = fh * (LL / 2) + t * TJA + jj;
            int gi = (b * LL + j) * 64 + c4;
            ((float4*)Kt)[fh * 1024 + jj * 64 + c4] = kg[gi];
            ((float4*)Vt)[fh * 1024 + jj * 64 + c4] = vg[gi];
        }
        // stage relation idx + mask (int32)
#pragma unroll
        for (int q2 = 0; q2 < 2; q2++) {
            int f  = tid + q2 * 256;            // 0..511
            int fh = f >> 8, ii = (f >> 4) & 15, jj = f & 15;
            int j  = fh * (LL / 2) + t * TJA + jj;
            size_t gi = (size_t)(b * LL + i0 + ii) * LL + j;
            ri[fh * 256 + ii * 16 + jj] = rel[gi];
            mk[fh * 256 + ii * 16 + jj] = relmask[gi];
        }
        __syncthreads();

        const float* Kth = Kt + hf * (16 * 256);
        const float* Vth = Vt + hf * (16 * 256);
        const int* rih = ri + hf * 256 + il * 16;
        const int* mkh = mk + hf * 256 + il * 16;

        // pass 1: scores + tile max
        float e[TJA];
        float tmax = -INFINITY;
#pragma unroll 4
        for (int jj = 0; jj < TJA; jj++) {
            const float4* kr4 = (const float4*)(Kth + jj * 256 + h * 32);
            float d0 = 0.f, d1 = 0.f, d2 = 0.f, d3 = 0.f;
#pragma unroll
            for (int d4 = 0; d4 < 8; d4++) {
                float4 kv = kr4[d4];
                d0 += ql[d4 * 4 + 0] * kv.x;
                d1 += ql[d4 * 4 + 1] * kv.y;
                d2 += ql[d4 * 4 + 2] * kv.z;
                d3 += ql[d4 * 4 + 3] * kv.w;
            }
            int r = rih[jj];
            float ee = (d0 + d1) + (d2 + d3) + qrow[r];
            ee = mkh[jj] ? -1e30f : ee;
            e[jj] = ee;
            tmax = fmaxf(tmax, ee);
        }

        // single rescale per tile (rare after warm-up)
        if (tmax > m) {
            float c = ex2f(m - tmax);
            s *= c;
#pragma unroll
            for (int d = 0; d < 32; d++) oc[d] *= c;
#pragma unroll 1
            for (int r = 0; r < RELN; r++) wr[r] *= c;
            m = tmax;
        }

        // pass 2: accumulate
#pragma unroll 4
        for (int jj = 0; jj < TJA; jj++) {
            float p = ex2f(e[jj] - m);
            s += p;
            wr[rih[jj]] += p;
            const float4* vr4 = (const float4*)(Vth + jj * 256 + h * 32);
#pragma unroll
            for (int d4 = 0; d4 < 8; d4++) {
                float4 vv = vr4[d4];
                oc[d4 * 4 + 0] += p * vv.x;
                oc[d4 * 4 + 1] += p * vv.y;
                oc[d4 * 4 + 2] += p * vv.z;
                oc[d4 * 4 + 3] += p * vv.w;
            }
        }
    }

    // ---- combine the two halves; add relation-value term; write out ----
    __syncthreads();
    float* cm  = Kt;               // 128
    float* cs  = Kt + 128;         // 128
    float* co  = Kt + 256;         // 128*32
    float* Evs = Vt;               // 3200 floats staged Ev

    for (int t2 = tid; t2 < RELN * 32; t2 += 256) Evs[t2] = Ev[t2];

    if (hf == 1) {
        cm[pr] = m; cs[pr] = s;
#pragma unroll
        for (int d4 = 0; d4 < 8; d4++) {
            float4 v4;
            v4.x = oc[d4 * 4 + 0]; v4.y = oc[d4 * 4 + 1];
            v4.z = oc[d4 * 4 + 2]; v4.w = oc[d4 * 4 + 3];
            *(float4*)(co + pr * 32 + d4 * 4) = v4;
        }
    }
    __syncthreads();
    if (hf == 0) {
        float m2 = cm[pr], s2 = cs[pr];
        float nm = fmaxf(m, m2);
        float c1 = ex2f(m - nm), c2 = ex2f(m2 - nm);
        float inv = 1.f / (s * c1 + s2 * c2);

        float of[32];
#pragma unroll
        for (int d4 = 0; d4 < 8; d4++) {
            float4 o2 = *(const float4*)(co + pr * 32 + d4 * 4);
            of[d4 * 4 + 0] = oc[d4 * 4 + 0] * c1 + o2.x * c2;
            of[d4 * 4 + 1] = oc[d4 * 4 + 1] * c1 + o2.y * c2;
            of[d4 * 4 + 2] = oc[d4 * 4 + 2] * c1 + o2.z * c2;
            of[d4 * 4 + 3] = oc[d4 * 4 + 3] * c1 + o2.w * c2;
        }

        const float* w0 = Wh + pr * 101;
        const float* w1 = Wh + (128 + pr) * 101;
#pragma unroll 2
        for (int r = 0; r < RELN; r++) {
            float wv = w0[r] * c1 + w1[r] * c2;
            const float4* ev4 = (const float4*)(Evs + r * 32);
#pragma unroll
            for (int d4 = 0; d4 < 8; d4++) {
                float4 ev = ev4[d4];
                of[d4 * 4 + 0] += wv * ev.x;
                of[d4 * 4 + 1] += wv * ev.y;
                of[d4 * 4 + 2] += wv * ev.z;
                of[d4 * 4 + 3] += wv * ev.w;
            }
        }

        float* op = O + (size_t)irow * HH + h * 32;
#pragma unroll
        for (int d4 = 0; d4 < 8; d4++) {
            float4 v4;
            v4.x = of[d4 * 4 + 0] * inv; v4.y = of[d4 * 4 + 1] * inv;
            v4.z = of[d4 * 4 + 2] * inv; v4.w = of[d4 * 4 + 3] * inv;
            *(float4*)(op + d4 * 4) = v4;
        }
    }
}

// ------------------------------------------------- Residual + LayerNorm ----
__global__ __launch_bounds__(256) void ln_kernel(
    const float* __restrict__ X, const float* __restrict__ Y,
    const float* __restrict__ g, const float* __restrict__ bta,
    float* __restrict__ Out)
{
    const int r = blockIdx.x;
    const int c = threadIdx.x;
    float v = X[(size_t)r * HH + c] + Y[(size_t)r * HH + c];
    float s1 = v, s2 = v * v;
#pragma unroll
    for (int o = 16; o; o >>= 1) {
        s1 += __shfl_xor_sync(0xffffffffu, s1, o);
        s2 += __shfl_xor_sync(0xffffffffu, s2, o);
    }
    __shared__ float r1[8], r2[8];
    if ((c & 31) == 0) { r1[c >> 5] = s1; r2[c >> 5] = s2; }
    __syncthreads();
    if (c < 32) {
        s1 = (c < 8) ? r1[c] : 0.f;
        s2 = (c < 8) ? r2[c] : 0.f;
#pragma unroll
        for (int o = 4; o; o >>= 1) {
            s1 += __shfl_xor_sync(0xffffffffu, s1, o);
            s2 += __shfl_xor_sync(0xffffffffu, s2, o);
        }
        if (c == 0) { r1[0] = s1; r2[0] = s2; }
    }
    __syncthreads();
    float mean = r1[0] * (1.f / HH);
    float var  = r2[0] * (1.f / HH) - mean * mean;
    Out[(size_t)r * HH + c] = (v - mean) * rsqrtf(var + EPSLN) * g[c] + bta[c];
}

// ------------------------------------------------------------- launcher ----
extern "C" void kernel_launch(void* const* d_in, const int* in_sizes, int n_in,
                              void* d_out, int out_size)
{
    const float* inputs = (const float*)d_in[0];
    const float* Wq  = (const float*)d_in[1];
    const float* Wk  = (const float*)d_in[2];
    const float* Wv  = (const float*)d_in[3];
    const float* Wo  = (const float*)d_in[4];
    const float* bo  = (const float*)d_in[5];
    const float* W1  = (const float*)d_in[6];
    const float* b1  = (const float*)d_in[7];
    const float* W2  = (const float*)d_in[8];
    const float* b2  = (const float*)d_in[9];
    const float* ln1g = (const float*)d_in[10];
    const float* ln1b = (const float*)d_in[11];
    const float* ln2g = (const float*)d_in[12];
    const float* ln2b = (const float*)d_in[13];
    const float* Ek  = (const float*)d_in[14];
    const float* Ev  = (const float*)d_in[15];
    const int*   rel = (const int*)d_in[16];
    const int*   rmask = (const int*)d_in[17];
    float* out = (float*)d_out;

    float *qb, *kb, *vb, *ab, *yb, *xb, *fb;
    cudaGetSymbolAddress((void**)&qb, g_qb);
    cudaGetSymbolAddress((void**)&kb, g_kb);
    cudaGetSymbolAddress((void**)&vb, g_vb);
    cudaGetSymbolAddress((void**)&ab, g_ab);
    cudaGetSymbolAddress((void**)&yb, g_yb);
    cudaGetSymbolAddress((void**)&xb, g_xb);
    cudaGetSymbolAddress((void**)&fb, g_fb);

    cudaFuncSetAttribute(attn_kernel,
                         cudaFuncAttributeMaxDynamicSharedMemorySize,
                         ATTN_SMEM_BYTES);

    for (int l = 0; l < NLAYER; l++) {
        const float* x = (l == 0) ? inputs : xb;
        const size_t wHH = (size_t)l * HH * HH;
        const size_t wHF = (size_t)l * HH * FFD;

        gemm_qkv_kernel<<<dim3(HH/BN, ROWS/BM, 3), 256>>>(
            x, Wq + wHH, Wk + wHH, Wv + wHH, qb, kb, vb);

        attn_kernel<<<dim3(LL/TI, BB), 256, ATTN_SMEM_BYTES>>>(qb, kb, vb, Ek, Ev, rel, rmask, ab);

        gemm_kernel<<<dim3(HH/BN, ROWS/BM), 256>>>(ab, Wo + wHH, bo + l*HH, yb, HH, HH, 0);
        ln_kernel<<<ROWS, HH>>>(x, yb, ln1g + l*HH, ln1b + l*HH, xb);

        gemm_kernel<<<dim3(FFD/BN, ROWS/BM), 256>>>(xb, W1 + wHF, b1 + l*FFD, fb, FFD, HH, 1);
        gemm_kernel<<<dim3(HH/BN, ROWS/BM), 256>>>(fb, W2 + wHF, b2 + l*HH, yb, HH, FFD, 0);
        ln_kernel<<<ROWS, HH>>>(xb, yb, ln2g + l*HH, ln2b + l*HH, (l == NLAYER-1) ? out : xb);
    }
}

// round 5
// speedup vs baseline: 1.7242x; 1.1208x over previous
#include <cuda_runtime.h>
#include <math.h>
#include <stdint.h>

// Problem constants
#define BB 2
#define LL 1024
#define HH 256
#define NHEAD 8
#define DHEAD 32
#define FFD 1024
#define NLAYER 2
#define RELN 100
#define EPSLN 1e-5f
// 1/sqrt(32) * log2(e)  (exp done in base 2)
#define QSCALE (0.17677669529663687f * 1.4426950408889634f)

#define ROWS (BB*LL)          // 2048

// ---------------- scratch (static device memory; no allocations allowed) ----
__device__ float g_qb[ROWS*HH];
__device__ float g_kb[ROWS*HH];
__device__ float g_vb[ROWS*HH];
__device__ float g_ab[ROWS*HH];
__device__ float g_yb[ROWS*HH];
__device__ float g_xb[ROWS*HH];
__device__ float g_fb[ROWS*FFD];

__device__ __forceinline__ float ex2f(float x) {
    float y;
    asm("ex2.approx.ftz.f32 %0, %1;" : "=f"(y) : "f"(x));
    return y;
}

__device__ __forceinline__ float tf32r(float x) {
    float y;
    asm("cvt.rna.tf32.f32 %0, %1;" : "=f"(y) : "f"(x));
    return y;
}

__device__ __forceinline__ void mma_tf32(
    float& c0, float& c1, float& c2, float& c3,
    uint32_t a0, uint32_t a1, uint32_t a2, uint32_t a3,
    uint32_t b0, uint32_t b1)
{
    asm volatile(
        "mma.sync.aligned.m16n8k8.row.col.f32.tf32.tf32.f32 "
        "{%0,%1,%2,%3}, {%4,%5,%6,%7}, {%8,%9}, {%0,%1,%2,%3};"
        : "+f"(c0), "+f"(c1), "+f"(c2), "+f"(c3)
        : "r"(a0), "r"(a1), "r"(a2), "r"(a3), "r"(b0), "r"(b1));
}

// ------------------------------------------------------- tf32 MMA GEMM -----
#define BM 64
#define BN 64
#define BKG 32
#define APAD 8
#define BPAD 8

__device__ __forceinline__ void gemm_tf32_body(
    const float* __restrict__ A, const float* __restrict__ B,
    const float* __restrict__ bias, float* __restrict__ C,
    int N, int K, int doRelu, int bm, int bn,
    float oscale, int roundOut)
{
    __shared__ float As[BKG][BM + APAD];   // [k][m]
    __shared__ float Bs[BKG][BN + BPAD];   // [k][n]

    const int tid  = threadIdx.x;
    const int warp = tid >> 5;
    const int lane = tid & 31;
    const int wm = (warp & 3) * 16;
    const int wn = (warp >> 2) * 32;
    const int g  = lane >> 2;
    const int tg = lane & 3;

    float acc[4][4];
#pragma unroll
    for (int i = 0; i < 4; i++)
#pragma unroll
        for (int j = 0; j < 4; j++) acc[i][j] = 0.f;

    const int ar0 = tid >> 3;
    const int ac0 = (tid & 7) * 4;
    const int br0 = tid >> 4;
    const int bc0 = (tid & 15) * 4;

    for (int k0 = 0; k0 < K; k0 += BKG) {
#pragma unroll
        for (int it = 0; it < 2; it++) {
            int arow = ar0 + it * 32;
            float4 av = *(const float4*)(A + (size_t)(bm + arow) * K + k0 + ac0);
            As[ac0 + 0][arow] = tf32r(av.x);
            As[ac0 + 1][arow] = tf32r(av.y);
            As[ac0 + 2][arow] = tf32r(av.z);
            As[ac0 + 3][arow] = tf32r(av.w);
            int brow = br0 + it * 16;
            float4 bv = *(const float4*)(B + (size_t)(k0 + brow) * N + bn + bc0);
            float4 bc;
            bc.x = tf32r(bv.x); bc.y = tf32r(bv.y);
            bc.z = tf32r(bv.z); bc.w = tf32r(bv.w);
            *(float4*)&Bs[brow][bc0] = bc;
        }
        __syncthreads();

#pragma unroll
        for (int ks = 0; ks < BKG; ks += 8) {
            uint32_t a0 = __float_as_uint(As[ks + tg    ][wm + g    ]);
            uint32_t a1 = __float_as_uint(As[ks + tg    ][wm + g + 8]);
            uint32_t a2 = __float_as_uint(As[ks + tg + 4][wm + g    ]);
            uint32_t a3 = __float_as_uint(As[ks + tg + 4][wm + g + 8]);
#pragma unroll
            for (int nt = 0; nt < 4; nt++) {
                uint32_t b0 = __float_as_uint(Bs[ks + tg    ][wn + nt * 8 + g]);
                uint32_t b1 = __float_as_uint(Bs[ks + tg + 4][wn + nt * 8 + g]);
                mma_tf32(acc[nt][0], acc[nt][1], acc[nt][2], acc[nt][3],
                         a0, a1, a2, a3, b0, b1);
            }
        }
        __syncthreads();
    }

    const int row0 = bm + wm + g;
    const int colb = bn + wn + 2 * tg;
#pragma unroll
    for (int nt = 0; nt < 4; nt++) {
        int col = colb + nt * 8;
        float b0v = 0.f, b1v = 0.f;
        if (bias) { b0v = bias[col]; b1v = bias[col + 1]; }
        float2 o0, o1;
        o0.x = acc[nt][0] * oscale + b0v; o0.y = acc[nt][1] * oscale + b1v;
        o1.x = acc[nt][2] * oscale + b0v; o1.y = acc[nt][3] * oscale + b1v;
        if (doRelu) {
            o0.x = fmaxf(o0.x, 0.f); o0.y = fmaxf(o0.y, 0.f);
            o1.x = fmaxf(o1.x, 0.f); o1.y = fmaxf(o1.y, 0.f);
        }
        if (roundOut) {
            o0.x = tf32r(o0.x); o0.y = tf32r(o0.y);
            o1.x = tf32r(o1.x); o1.y = tf32r(o1.y);
        }
        *(float2*)(C + (size_t)row0 * N + col)       = o0;
        *(float2*)(C + (size_t)(row0 + 8) * N + col) = o1;
    }
}

__global__ __launch_bounds__(256) void gemm_kernel(
    const float* __restrict__ A, const float* __restrict__ B,
    const float* __restrict__ bias, float* __restrict__ C,
    int N, int K, int doRelu)
{
    gemm_tf32_body(A, B, bias, C, N, K, doRelu,
                   blockIdx.y * BM, blockIdx.x * BN, 1.f, 0);
}

// fused QKV: z selects weight/output. Q output pre-scaled by QSCALE;
// Q,K,V all written tf32-rounded (consumed only by the mma attention).
__global__ __launch_bounds__(256) void gemm_qkv_kernel(
    const float* __restrict__ A,
    const float* __restrict__ Bq, const float* __restrict__ Bk,
    const float* __restrict__ Bv,
    float* __restrict__ Cq, float* __restrict__ Ck, float* __restrict__ Cv)
{
    const float* B = (blockIdx.z == 0) ? Bq : (blockIdx.z == 1) ? Bk : Bv;
    float*       C = (blockIdx.z == 0) ? Cq : (blockIdx.z == 1) ? Ck : Cv;
    float oscale = (blockIdx.z == 0) ? QSCALE : 1.f;
    gemm_tf32_body(A, B, nullptr, C, HH, HH, 0,
                   blockIdx.y * BM, blockIdx.x * BN, oscale, 1);
}

// ----------------------------------------------------- MMA Attention -------
// Block: 16 i-rows x 8 heads x 1 batch, j processed in 32-wide tiles.
// Warp w = head w for MMA phases; threads 0..127 are (h=tid>>4, il=tid&15)
// row owners for the scalar softmax/histogram phase.
#define TI 16
#define TJ 32
#define EPR 36      // EP row stride (i)
#define EPH 584     // EP head stride (16*36 padded to shift banks by 8)
#define KSR 260     // K tile row stride (j)
#define VSR 264     // V tile row stride (j)

// smem float offsets
#define SM_QREL 0                        // 128*101 = 12928
#define SM_EP   12928                    // 8*EPH   = 4672  (Q stage -> e/p -> o)
#define SM_KS   17600                    // 32*260  = 8320  (K tile; Ev at end)
#define SM_VS   25920                    // 32*264  = 8448
#define SM_RI   34368                    // 512 ints
#define SM_MK   34880                    // 512 ints
#define SM_CS   35392                    // 128
#define SM_W    35520                    // 128*101 = 12928
#define ATTN_SMEM_FLOATS 48448
#define ATTN_SMEM_BYTES  (ATTN_SMEM_FLOATS*4)   // 193792 B

__global__ __launch_bounds__(256, 1) void attn_kernel(
    const float* __restrict__ Q, const float* __restrict__ Kk,
    const float* __restrict__ V, const float* __restrict__ Ek,
    const float* __restrict__ Ev, const int* __restrict__ rel,
    const int* __restrict__ relmask, float* __restrict__ O)
{
    extern __shared__ float sm[];
    float* QREL = sm + SM_QREL;
    float* EP   = sm + SM_EP;
    float* Ks   = sm + SM_KS;
    float* Vs   = sm + SM_VS;
    int*   ri   = (int*)(sm + SM_RI);
    int*   mk   = (int*)(sm + SM_MK);
    float* Cs   = sm + SM_CS;
    float* Wh   = sm + SM_W;

    const int tid  = threadIdx.x;
    const int b    = blockIdx.y;
    const int i0   = blockIdx.x * TI;
    const int row0 = b * LL + i0;
    const int w    = tid >> 5;
    const int lane = tid & 31;
    const int g    = lane >> 2;
    const int tg   = lane & 3;

    // ---- QREL precompute: qrel[pr][r] = q_scaled(pr) . Ek[r] ----
    {
        const int pr = tid & 127;
        const int h  = pr >> 4, il = pr & 15;
        float ql[32];
        const float4* qp = (const float4*)(Q + (size_t)(row0 + il) * HH + h * DHEAD);
#pragma unroll
        for (int d4 = 0; d4 < 8; d4++) {
            float4 v4 = qp[d4];
            ql[d4*4+0] = v4.x; ql[d4*4+1] = v4.y;
            ql[d4*4+2] = v4.z; ql[d4*4+3] = v4.w;
        }
        float* qrow = QREL + pr * 101;
        const int r0 = (tid >> 7) * 50;
#pragma unroll 2
        for (int r = r0; r < r0 + 50; r++) {
            const float4* e4 = (const float4*)(Ek + r * 32);
            float d0 = 0.f, d1 = 0.f, d2 = 0.f, d3 = 0.f;
#pragma unroll
            for (int d4 = 0; d4 < 8; d4++) {
                float4 ev = e4[d4];
                d0 += ql[d4*4+0] * ev.x; d1 += ql[d4*4+1] * ev.y;
                d2 += ql[d4*4+2] * ev.z; d3 += ql[d4*4+3] * ev.w;
            }
            qrow[r] = (d0 + d1) + (d2 + d3);
        }
    }

    // ---- stage Q (already scaled+tf32) into EP region ----
#pragma unroll
    for (int q = 0; q < 4; q++) {
        int f  = tid + q * 256;          // 0..1023 float4 slots (16 rows x 64)
        int i  = f >> 6;
        int hc = f & 63;
        int hh = hc >> 3, d4 = hc & 7;
        float4 v4 = ((const float4*)Q)[(size_t)(row0 + i) * 64 + hc];
        *(float4*)&EP[hh * EPH + i * EPR + d4 * 4] = v4;
    }

    // ---- zero relation histogram ----
    if (tid < 128) {
        float* wrp = Wh + tid * 101;
#pragma unroll 4
        for (int r = 0; r < RELN; r++) wrp[r] = 0.f;
    }
    __syncthreads();

    // ---- preload Q fragments (loop-invariant A operand) ----
    uint32_t qa[4][4];
    {
        const float* eph = EP + w * EPH;
#pragma unroll
        for (int ks = 0; ks < 4; ks++) {
            qa[ks][0] = __float_as_uint(eph[ g      * EPR + tg     + 8*ks]);
            qa[ks][1] = __float_as_uint(eph[(g + 8) * EPR + tg     + 8*ks]);
            qa[ks][2] = __float_as_uint(eph[ g      * EPR + tg + 4 + 8*ks]);
            qa[ks][3] = __float_as_uint(eph[(g + 8) * EPR + tg + 4 + 8*ks]);
        }
    }

    float m = -INFINITY, s = 0.f;
    float oa[4][4];
#pragma unroll
    for (int ns = 0; ns < 4; ns++)
#pragma unroll
        for (int c = 0; c < 4; c++) oa[ns][c] = 0.f;

    float* qrow_s = QREL + (tid & 127) * 101;
    float* wrp    = Wh   + (tid & 127) * 101;
    const float4* kg4 = (const float4*)Kk;
    const float4* vg4 = (const float4*)V;

    for (int t = 0; t < LL / TJ; t++) {
        __syncthreads();
        const int j0 = t * TJ;
        // stage K/V tiles (32 j x 256 cols each)
#pragma unroll
        for (int q = 0; q < 8; q++) {
            int f  = tid + q * 256;      // 0..2047 float4 slots
            int jj = f >> 6;
            int c4 = f & 63;
            int gi = (b * LL + j0 + jj) * 64 + c4;
            *(float4*)&Ks[jj * KSR + c4 * 4] = kg4[gi];
            *(float4*)&Vs[jj * VSR + c4 * 4] = vg4[gi];
        }
        // stage relation idx + mask
#pragma unroll
        for (int q = 0; q < 2; q++) {
            int f  = tid + q * 256;      // 0..511
            int ii = f >> 5, jj = f & 31;
            size_t gi = (size_t)(row0 + ii) * LL + j0 + jj;
            ri[ii * 32 + jj] = rel[gi];
            mk[ii * 32 + jj] = relmask[gi];
        }
        __syncthreads();

        // ---- score MMA: e(16x32) = Q(16x32) . K^T ----
        {
            float* eph = EP + w * EPH;
            const float* ksh = Ks + w * 32;
            float ec[4][4];
#pragma unroll
            for (int ns = 0; ns < 4; ns++)
#pragma unroll
                for (int c = 0; c < 4; c++) ec[ns][c] = 0.f;
#pragma unroll
            for (int ns = 0; ns < 4; ns++) {
                const float* kb = ksh + (ns * 8 + g) * KSR;
#pragma unroll
                for (int ks = 0; ks < 4; ks++) {
                    uint32_t b0 = __float_as_uint(kb[tg     + 8*ks]);
                    uint32_t b1 = __float_as_uint(kb[tg + 4 + 8*ks]);
                    mma_tf32(ec[ns][0], ec[ns][1], ec[ns][2], ec[ns][3],
                             qa[ks][0], qa[ks][1], qa[ks][2], qa[ks][3], b0, b1);
                }
            }
#pragma unroll
            for (int ns = 0; ns < 4; ns++) {
                *(float2*)&eph[ g      * EPR + ns * 8 + 2*tg] = make_float2(ec[ns][0], ec[ns][1]);
                *(float2*)&eph[(g + 8) * EPR + ns * 8 + 2*tg] = make_float2(ec[ns][2], ec[ns][3]);
            }
        }
        __syncthreads();

        // ---- scalar phase: bias + mask + online softmax + histogram ----
        if (tid < 128) {
            const int il = tid & 15;
            float* erow = EP + (tid >> 4) * EPH + il * EPR;
            const int* rr = ri + il * 32;
            const int* mrow = mk + il * 32;
            float ee[TJ];
            float tmax = -INFINITY;
#pragma unroll
            for (int jj = 0; jj < TJ; jj++) {
                float e = erow[jj] + qrow_s[rr[jj]];
                e = mrow[jj] ? -1e30f : e;
                ee[jj] = e;
                tmax = fmaxf(tmax, e);
            }
            float c = 1.f;
            if (tmax > m) {
                c = ex2f(m - tmax);
                m = tmax;
                s *= c;
#pragma unroll 4
                for (int r = 0; r < RELN; r++) wrp[r] *= c;
            }
            Cs[tid] = c;
            float ss = 0.f;
#pragma unroll
            for (int jj = 0; jj < TJ; jj++) {
                float p = ex2f(ee[jj] - m);
                ss += p;
                wrp[rr[jj]] += p;
                erow[jj] = tf32r(p);
            }
            s += ss;
        }
        __syncthreads();

        // ---- AV MMA: o(16x32) = c*o + P(16x32) . V(32x32) ----
        {
            const float* eph = EP + w * EPH;
            float cg0 = Cs[w * 16 + g];
            float cg1 = Cs[w * 16 + g + 8];
#pragma unroll
            for (int ns = 0; ns < 4; ns++) {
                oa[ns][0] *= cg0; oa[ns][1] *= cg0;
                oa[ns][2] *= cg1; oa[ns][3] *= cg1;
            }
#pragma unroll
            for (int ks = 0; ks < 4; ks++) {
                uint32_t pa0 = __float_as_uint(eph[ g      * EPR + tg     + 8*ks]);
                uint32_t pa1 = __float_as_uint(eph[(g + 8) * EPR + tg     + 8*ks]);
                uint32_t pa2 = __float_as_uint(eph[ g      * EPR + tg + 4 + 8*ks]);
                uint32_t pa3 = __float_as_uint(eph[(g + 8) * EPR + tg + 4 + 8*ks]);
                const float* vb0 = Vs + (ks * 8 + tg    ) * VSR + w * 32;
                const float* vb1 = Vs + (ks * 8 + tg + 4) * VSR + w * 32;
#pragma unroll
                for (int ns = 0; ns < 4; ns++) {
                    uint32_t b0 = __float_as_uint(vb0[ns * 8 + g]);
                    uint32_t b1 = __float_as_uint(vb1[ns * 8 + g]);
                    mma_tf32(oa[ns][0], oa[ns][1], oa[ns][2], oa[ns][3],
                             pa0, pa1, pa2, pa3, b0, b1);
                }
            }
        }
    }

    // ---- epilogue: o frags -> smem; add relation-value term; normalize ----
    __syncthreads();
    {
        float* eph = EP + w * EPH;
#pragma unroll
        for (int ns = 0; ns < 4; ns++) {
            *(float2*)&eph[ g      * EPR + ns * 8 + 2*tg] = make_float2(oa[ns][0], oa[ns][1]);
            *(float2*)&eph[(g + 8) * EPR + ns * 8 + 2*tg] = make_float2(oa[ns][2], oa[ns][3]);
        }
    }
    // stage Ev into Ks region (done with K tiles)
    for (int f = tid; f < RELN * 32; f += 256) Ks[f] = Ev[f];
    __syncthreads();

    if (tid < 128) {
        const int h = tid >> 4, il = tid & 15;
        const float* orow = EP + h * EPH + il * EPR;
        float of[32];
#pragma unroll
        for (int d = 0; d < 32; d++) of[d] = orow[d];
#pragma unroll 2
        for (int r = 0; r < RELN; r++) {
            float wv = wrp[r];
            const float4* ev4 = (const float4*)(Ks + r * 32);
#pragma unroll
            for (int d4 = 0; d4 < 8; d4++) {
                float4 ev = ev4[d4];
                of[d4*4+0] += wv * ev.x; of[d4*4+1] += wv * ev.y;
                of[d4*4+2] += wv * ev.z; of[d4*4+3] += wv * ev.w;
            }
        }
        float inv = 1.f / s;
        float* op = O + (size_t)(row0 + il) * HH + h * 32;
#pragma unroll
        for (int d4 = 0; d4 < 8; d4++) {
            float4 v4;
            v4.x = of[d4*4+0] * inv; v4.y = of[d4*4+1] * inv;
            v4.z = of[d4*4+2] * inv; v4.w = of[d4*4+3] * inv;
            *(float4*)(op + d4 * 4) = v4;
        }
    }
}

// ------------------------------------------------- Residual + LayerNorm ----
__global__ __launch_bounds__(256) void ln_kernel(
    const float* __restrict__ X, const float* __restrict__ Y,
    const float* __restrict__ g, const float* __restrict__ bta,
    float* __restrict__ Out)
{
    const int r = blockIdx.x;
    const int c = threadIdx.x;
    float v = X[(size_t)r * HH + c] + Y[(size_t)r * HH + c];
    float s1 = v, s2 = v * v;
#pragma unroll
    for (int o = 16; o; o >>= 1) {
        s1 += __shfl_xor_sync(0xffffffffu, s1, o);
        s2 += __shfl_xor_sync(0xffffffffu, s2, o);
    }
    __shared__ float r1[8], r2[8];
    if ((c & 31) == 0) { r1[c >> 5] = s1; r2[c >> 5] = s2; }
    __syncthreads();
    if (c < 32) {
        s1 = (c < 8) ? r1[c] : 0.f;
        s2 = (c < 8) ? r2[c] : 0.f;
#pragma unroll
        for (int o = 4; o; o >>= 1) {
            s1 += __shfl_xor_sync(0xffffffffu, s1, o);
            s2 += __shfl_xor_sync(0xffffffffu, s2, o);
        }
        if (c == 0) { r1[0] = s1; r2[0] = s2; }
    }
    __syncthreads();
    float mean = r1[0] * (1.f / HH);
    float var  = r2[0] * (1.f / HH) - mean * mean;
    Out[(size_t)r * HH + c] = (v - mean) * rsqrtf(var + EPSLN) * g[c] + bta[c];
}

// ------------------------------------------------------------- launcher ----
extern "C" void kernel_launch(void* const* d_in, const int* in_sizes, int n_in,
                              void* d_out, int out_size)
{
    const float* inputs = (const float*)d_in[0];
    const float* Wq  = (const float*)d_in[1];
    const float* Wk  = (const float*)d_in[2];
    const float* Wv  = (const float*)d_in[3];
    const float* Wo  = (const float*)d_in[4];
    const float* bo  = (const float*)d_in[5];
    const float* W1  = (const float*)d_in[6];
    const float* b1  = (const float*)d_in[7];
    const float* W2  = (const float*)d_in[8];
    const float* b2  = (const float*)d_in[9];
    const float* ln1g = (const float*)d_in[10];
    const float* ln1b = (const float*)d_in[11];
    const float* ln2g = (const float*)d_in[12];
    const float* ln2b = (const float*)d_in[13];
    const float* Ek  = (const float*)d_in[14];
    const float* Ev  = (const float*)d_in[15];
    const int*   rel = (const int*)d_in[16];
    const int*   rmask = (const int*)d_in[17];
    float* out = (float*)d_out;

    float *qb, *kb, *vb, *ab, *yb, *xb, *fb;
    cudaGetSymbolAddress((void**)&qb, g_qb);
    cudaGetSymbolAddress((void**)&kb, g_kb);
    cudaGetSymbolAddress((void**)&vb, g_vb);
    cudaGetSymbolAddress((void**)&ab, g_ab);
    cudaGetSymbolAddress((void**)&yb, g_yb);
    cudaGetSymbolAddress((void**)&xb, g_xb);
    cudaGetSymbolAddress((void**)&fb, g_fb);

    cudaFuncSetAttribute(attn_kernel,
                         cudaFuncAttributeMaxDynamicSharedMemorySize,
                         ATTN_SMEM_BYTES);

    for (int l = 0; l < NLAYER; l++) {
        const float* x = (l == 0) ? inputs : xb;
        const size_t wHH = (size_t)l * HH * HH;
        const size_t wHF = (size_t)l * HH * FFD;

        gemm_qkv_kernel<<<dim3(HH/BN, ROWS/BM, 3), 256>>>(
            x, Wq + wHH, Wk + wHH, Wv + wHH, qb, kb, vb);

        attn_kernel<<<dim3(LL/TI, BB), 256, ATTN_SMEM_BYTES>>>(qb, kb, vb, Ek, Ev, rel, rmask, ab);

        gemm_kernel<<<dim3(HH/BN, ROWS/BM), 256>>>(ab, Wo + wHH, bo + l*HH, yb, HH, HH, 0);
        ln_kernel<<<ROWS, HH>>>(x, yb, ln1g + l*HH, ln1b + l*HH, xb);

        gemm_kernel<<<dim3(FFD/BN, ROWS/BM), 256>>>(xb, W1 + wHF, b1 + l*FFD, fb, FFD, HH, 1);
        gemm_kernel<<<dim3(HH/BN, ROWS/BM), 256>>>(fb, W2 + wHF, b2 + l*HH, yb, HH, FFD, 0);
        ln_kernel<<<ROWS, HH>>>(xb, yb, ln2g + l*HH, ln2b + l*HH, (l == NLAYER-1) ? out : xb);
    }
}